// round 1
// baseline (speedup 1.0000x reference)
#include <cuda_runtime.h>
#include <math.h>

#define BATCH  4
#define LSEQ   4096
#define DMODEL 1024
#define DINNER 2048
#define DTR    64
#define NST    16
#define XDBLC  96   // dt_rank + 2*N

// ---------------- scratch (device globals; no allocations allowed) ----------
__device__ float g_xr  [(size_t)BATCH * LSEQ * (2 * DINNER)];  // [B,L,4096] in-proj out (x | res)
__device__ float g_xc  [(size_t)BATCH * LSEQ * DINNER];        // conv+silu out -> y (in place) -> gated y (in place)
__device__ float g_xdbl[(size_t)BATCH * LSEQ * XDBLC];         // [B,L,96]
__device__ float g_dt  [(size_t)BATCH * LSEQ * DINNER];        // softplus delta

// ---------------- generic tiled SGEMM: C = A@B (+bias) (+softplus) ----------
#define BM 128
#define BN 128
#define BK 16
#define TM 8
#define TN 8

__global__ __launch_bounds__(256)
void sgemm_kernel(const float* __restrict__ A, const float* __restrict__ B,
                  const float* __restrict__ bias, float* __restrict__ C,
                  int M, int N, int K, int lda, int ldb, int ldc, int epi)
{
    __shared__ float As[BK][BM];
    __shared__ float Bs[BK][BN];

    const int tid = threadIdx.x;
    const int bm  = blockIdx.y * BM;
    const int bn  = blockIdx.x * BN;

    // A-tile loader: 128 rows x 16 cols, float4 along K
    const int aRow = tid / 4;          // 0..63 (x2 with +64 stride)
    const int aCol = (tid % 4) * 4;    // 0,4,8,12
    // B-tile loader: 16 rows x 128 cols, scalar (N-guarded)
    const int bRow = tid / 32;         // 0..7 (x2 with +8 stride)
    const int bCol = (tid % 32) * 4;   // 0..124

    const int tr = (tid / 16) * TM;
    const int tc = (tid % 16) * TN;

    float acc[TM][TN];
    #pragma unroll
    for (int i = 0; i < TM; i++)
        #pragma unroll
        for (int j = 0; j < TN; j++) acc[i][j] = 0.f;

    float regM[TM], regN[TN];

    for (int kt = 0; kt < K; kt += BK) {
        #pragma unroll
        for (int r = 0; r < 2; r++) {
            const int m = aRow + r * 64;
            const float4 v = *(const float4*)(&A[(size_t)(bm + m) * lda + kt + aCol]);
            As[aCol + 0][m] = v.x;
            As[aCol + 1][m] = v.y;
            As[aCol + 2][m] = v.z;
            As[aCol + 3][m] = v.w;
        }
        #pragma unroll
        for (int r = 0; r < 2; r++) {
            const int k = bRow + r * 8;
            #pragma unroll
            for (int j = 0; j < 4; j++) {
                const int n = bn + bCol + j;
                Bs[k][bCol + j] = (n < N) ? B[(size_t)(kt + k) * ldb + n] : 0.f;
            }
        }
        __syncthreads();

        #pragma unroll
        for (int k = 0; k < BK; k++) {
            #pragma unroll
            for (int i = 0; i < TM; i++) regM[i] = As[k][tr + i];
            #pragma unroll
            for (int j = 0; j < TN; j++) regN[j] = Bs[k][tc + j];
            #pragma unroll
            for (int i = 0; i < TM; i++)
                #pragma unroll
                for (int j = 0; j < TN; j++)
                    acc[i][j] = fmaf(regM[i], regN[j], acc[i][j]);
        }
        __syncthreads();
    }

    #pragma unroll
    for (int i = 0; i < TM; i++) {
        const size_t row = (size_t)(bm + tr + i) * ldc;
        #pragma unroll
        for (int j = 0; j < TN; j++) {
            const int n = bn + tc + j;
            if (n >= N) continue;
            float v = acc[i][j];
            if (bias) v += bias[n];
            if (epi == 1) {                 // softplus
                v = (v > 20.f) ? v : log1pf(expf(v));
            }
            C[row + n] = v;
        }
    }
}

// ---------------- causal depthwise conv (K=4) + SiLU --------------------
__global__ __launch_bounds__(256)
void conv_silu_kernel(const float* __restrict__ conv_w, const float* __restrict__ conv_b)
{
    const size_t total = (size_t)BATCH * LSEQ * DINNER;
    size_t idx = (size_t)blockIdx.x * blockDim.x + threadIdx.x;
    if (idx >= total) return;
    const int d  = (int)(idx % DINNER);
    const int l  = (int)((idx / DINNER) % LSEQ);
    const int b  = (int)(idx / ((size_t)DINNER * LSEQ));

    float acc = conv_b[d];
    #pragma unroll
    for (int k = 0; k < 4; k++) {
        const int ls = l - 3 + k;
        if (ls >= 0)
            acc = fmaf(conv_w[d * 4 + k],
                       g_xr[((size_t)b * LSEQ + ls) * (2 * DINNER) + d], acc);
    }
    g_xc[idx] = acc / (1.f + expf(-acc));   // silu
}

// ---------------- sequential selective scan over L ----------------------
// one thread per (b, d) channel; y written in place over g_xc (includes +x*D)
__global__ __launch_bounds__(256)
void scan_kernel(const float* __restrict__ A_log, const float* __restrict__ D_par)
{
    const int d = blockIdx.x * blockDim.x + threadIdx.x;   // 0..2047
    const int b = blockIdx.y;

    float A[NST];
    #pragma unroll
    for (int n = 0; n < NST; n++) A[n] = -expf(A_log[d * NST + n]);
    float h[NST];
    #pragma unroll
    for (int n = 0; n < NST; n++) h[n] = 0.f;
    const float Dp = D_par[d];

    const float* xdb = g_xdbl + (size_t)b * LSEQ * XDBLC;

    for (int l = 0; l < LSEQ; l++) {
        const size_t base = ((size_t)b * LSEQ + l) * DINNER + d;
        const float dt = g_dt[base];
        const float xt = g_xc[base];
        const float* BC = xdb + (size_t)l * XDBLC + DTR;   // B at [64..80), C at [80..96)
        const float dtx = dt * xt;
        float yt = 0.f;
        #pragma unroll
        for (int n = 0; n < NST; n++) {
            const float dA = expf(dt * A[n]);
            h[n] = fmaf(h[n], dA, dtx * BC[n]);
            yt   = fmaf(h[n], BC[NST + n], yt);
        }
        g_xc[base] = fmaf(xt, Dp, yt);
    }
}

// ---------------- gating: y *= silu(res) (in place) ---------------------
__global__ __launch_bounds__(256)
void gate_kernel()
{
    const size_t total = (size_t)BATCH * LSEQ * DINNER;
    size_t idx = (size_t)blockIdx.x * blockDim.x + threadIdx.x;
    if (idx >= total) return;
    const int d = (int)(idx % DINNER);
    const size_t bl = idx / DINNER;
    const float r = g_xr[bl * (2 * DINNER) + DINNER + d];
    g_xc[idx] *= r / (1.f + expf(-r));
}

// ---------------- launch -------------------------------------------------
extern "C" void kernel_launch(void* const* d_in, const int* in_sizes, int n_in,
                              void* d_out, int out_size)
{
    const float* x      = (const float*)d_in[0];
    const float* W_in   = (const float*)d_in[1];
    const float* b_in   = (const float*)d_in[2];
    const float* conv_w = (const float*)d_in[3];
    const float* conv_b = (const float*)d_in[4];
    const float* W_x    = (const float*)d_in[5];
    const float* W_dt   = (const float*)d_in[6];
    const float* b_dt   = (const float*)d_in[7];
    const float* A_log  = (const float*)d_in[8];
    const float* D_par  = (const float*)d_in[9];
    const float* W_out  = (const float*)d_in[10];
    const float* b_out  = (const float*)d_in[11];
    float* out = (float*)d_out;

    float *xr, *xc, *xdbl, *dt;
    cudaGetSymbolAddress((void**)&xr,   g_xr);
    cudaGetSymbolAddress((void**)&xc,   g_xc);
    cudaGetSymbolAddress((void**)&xdbl, g_xdbl);
    cudaGetSymbolAddress((void**)&dt,   g_dt);

    const int M = BATCH * LSEQ;   // 16384

    // 1) in-projection: [M,1024] @ [1024,4096] -> g_xr
    sgemm_kernel<<<dim3((2 * DINNER) / BN, M / BM), 256>>>(
        x, W_in, b_in, xr, M, 2 * DINNER, DMODEL, DMODEL, 2 * DINNER, 2 * DINNER, 0);

    // 2) causal depthwise conv + silu -> g_xc
    {
        const size_t total = (size_t)M * DINNER;
        conv_silu_kernel<<<(unsigned)((total + 255) / 256), 256>>>(conv_w, conv_b);
    }

    // 3) x_dbl: [M,2048] @ [2048,96] -> g_xdbl
    sgemm_kernel<<<dim3((XDBLC + BN - 1) / BN, M / BM), 256>>>(
        xc, W_x, nullptr, xdbl, M, XDBLC, DINNER, DINNER, XDBLC, XDBLC, 0);

    // 4) delta: softplus([M,64] @ [64,2048] + b_dt) -> g_dt
    sgemm_kernel<<<dim3(DINNER / BN, M / BM), 256>>>(
        xdbl, W_dt, b_dt, dt, M, DINNER, DTR, XDBLC, DINNER, DINNER, 1);

    // 5) selective scan (y in place over g_xc, includes +x*D)
    scan_kernel<<<dim3(DINNER / 256, BATCH), 256>>>(A_log, D_par);

    // 6) gate with silu(res) (in place)
    {
        const size_t total = (size_t)M * DINNER;
        gate_kernel<<<(unsigned)((total + 255) / 256), 256>>>();
    }

    // 7) out-projection: [M,2048] @ [2048,1024] + b_out -> d_out
    sgemm_kernel<<<dim3(DMODEL / BN, M / BM), 256>>>(
        xc, W_out, b_out, out, M, DMODEL, DINNER, DINNER, DMODEL, DMODEL, 0);
}

// round 2
// speedup vs baseline: 1.1767x; 1.1767x over previous
#include <cuda_runtime.h>
#include <math.h>
#include <stdint.h>

#define BATCH  4
#define LSEQ   4096
#define DMODEL 1024
#define DINNER 2048
#define DTR    64
#define NST    16
#define XDBLC  96   // dt_rank + 2*N

// ---------------- scratch (device globals) ----------------
__device__ float g_xr  [(size_t)BATCH * LSEQ * (2 * DINNER)];  // in-proj out (x | res)
__device__ float g_xc  [(size_t)BATCH * LSEQ * DINNER];        // conv+silu -> y(gated) in place
__device__ float g_xdbl[(size_t)BATCH * LSEQ * XDBLC];
__device__ float g_dt  [(size_t)BATCH * LSEQ * DINNER];

// ---------------- tf32 tensor-core GEMM (2xTF32: A split hi/lo) ------------
#define BM 128
#define BN 128
#define BKK 32
#define AS_LD 36
#define BS_LD 132

__device__ __forceinline__ uint32_t f2tf(float f) {
    uint32_t r; asm("cvt.rna.tf32.f32 %0, %1;" : "=r"(r) : "f"(f)); return r;
}

__device__ __forceinline__ void mma8(float* c,
    uint32_t a0, uint32_t a1, uint32_t a2, uint32_t a3, uint32_t b0, uint32_t b1)
{
    asm volatile(
        "mma.sync.aligned.m16n8k8.row.col.f32.tf32.tf32.f32 "
        "{%0,%1,%2,%3}, {%4,%5,%6,%7}, {%8,%9}, {%0,%1,%2,%3};"
        : "+f"(c[0]), "+f"(c[1]), "+f"(c[2]), "+f"(c[3])
        : "r"(a0), "r"(a1), "r"(a2), "r"(a3), "r"(b0), "r"(b1));
}

// C[M,N] = A[M,K] @ B[K,N] (+bias) (+softplus if epi==1)
// M % 128 == 0, K % 32 == 0; N arbitrary (guarded).
__global__ __launch_bounds__(256)
void mma_gemm(const float* __restrict__ A, const float* __restrict__ B,
              const float* __restrict__ bias, float* __restrict__ C,
              int M, int N, int K, int lda, int ldb, int ldc, int epi)
{
    __shared__ float As[BM][AS_LD];    // raw fp32 (split at frag load)
    __shared__ float Bs[BKK][BS_LD];   // tf32-rounded

    const int tid = threadIdx.x;
    const int bm = blockIdx.y * BM;
    const int bn = blockIdx.x * BN;

    const int wid = tid >> 5, lane = tid & 31;
    const int wm = wid >> 1, wn = wid & 1;         // 4 x 2 warps
    const int qr = lane >> 2, qc = lane & 3;

    float acc[2][8][4];
    #pragma unroll
    for (int i = 0; i < 2; i++)
        #pragma unroll
        for (int j = 0; j < 8; j++)
            #pragma unroll
            for (int e = 0; e < 4; e++) acc[i][j][e] = 0.f;

    float4 ra[4], rb[4];

    // ---- loaders (gmem -> regs) ----
    auto loadA = [&](int kt) {
        #pragma unroll
        for (int t = 0; t < 4; t++) {
            const int f4 = tid + t * 256;
            const int r = f4 >> 3, c = (f4 & 7) * 4;
            ra[t] = *(const float4*)(A + (size_t)(bm + r) * lda + kt + c);
        }
    };
    auto loadB = [&](int kt) {
        #pragma unroll
        for (int t = 0; t < 4; t++) {
            const int f4 = tid + t * 256;
            const int k = f4 >> 5, c = (f4 & 31) * 4;
            const int n = bn + c;
            const float* p = B + (size_t)(kt + k) * ldb + n;
            if (n + 3 < N) {
                rb[t] = *(const float4*)p;
            } else {
                float4 v;
                v.x = (n + 0 < N) ? p[0] : 0.f;
                v.y = (n + 1 < N) ? p[1] : 0.f;
                v.z = (n + 2 < N) ? p[2] : 0.f;
                v.w = (n + 3 < N) ? p[3] : 0.f;
                rb[t] = v;
            }
        }
    };
    auto stS = [&]() {
        #pragma unroll
        for (int t = 0; t < 4; t++) {
            const int f4 = tid + t * 256;
            const int r = f4 >> 3, c = (f4 & 7) * 4;
            As[r][c + 0] = ra[t].x; As[r][c + 1] = ra[t].y;
            As[r][c + 2] = ra[t].z; As[r][c + 3] = ra[t].w;
            const int k = f4 >> 5, cb = (f4 & 31) * 4;
            Bs[k][cb + 0] = __uint_as_float(f2tf(rb[t].x));
            Bs[k][cb + 1] = __uint_as_float(f2tf(rb[t].y));
            Bs[k][cb + 2] = __uint_as_float(f2tf(rb[t].z));
            Bs[k][cb + 3] = __uint_as_float(f2tf(rb[t].w));
        }
    };

    loadA(0); loadB(0);

    for (int kt = 0; kt < K; kt += BKK) {
        stS();
        __syncthreads();
        if (kt + BKK < K) { loadA(kt + BKK); loadB(kt + BKK); }

        #pragma unroll
        for (int kk = 0; kk < BKK; kk += 8) {
            uint32_t ah[2][4], al[2][4];
            #pragma unroll
            for (int tm = 0; tm < 2; tm++) {
                const int r0 = wm * 32 + tm * 16 + qr;
                const float x0 = As[r0][kk + qc];
                const float x1 = As[r0 + 8][kk + qc];
                const float x2 = As[r0][kk + qc + 4];
                const float x3 = As[r0 + 8][kk + qc + 4];
                ah[tm][0] = f2tf(x0); al[tm][0] = f2tf(x0 - __uint_as_float(ah[tm][0]));
                ah[tm][1] = f2tf(x1); al[tm][1] = f2tf(x1 - __uint_as_float(ah[tm][1]));
                ah[tm][2] = f2tf(x2); al[tm][2] = f2tf(x2 - __uint_as_float(ah[tm][2]));
                ah[tm][3] = f2tf(x3); al[tm][3] = f2tf(x3 - __uint_as_float(ah[tm][3]));
            }
            #pragma unroll
            for (int tn = 0; tn < 8; tn++) {
                const int col = wn * 64 + tn * 8 + qr;
                const uint32_t b0 = __float_as_uint(Bs[kk + qc][col]);
                const uint32_t b1 = __float_as_uint(Bs[kk + qc + 4][col]);
                #pragma unroll
                for (int tm = 0; tm < 2; tm++) {
                    mma8(acc[tm][tn], al[tm][0], al[tm][1], al[tm][2], al[tm][3], b0, b1);
                    mma8(acc[tm][tn], ah[tm][0], ah[tm][1], ah[tm][2], ah[tm][3], b0, b1);
                }
            }
        }
        __syncthreads();
    }

    // ---- epilogue ----
    #pragma unroll
    for (int tm = 0; tm < 2; tm++) {
        const int r0 = bm + wm * 32 + tm * 16 + qr;
        #pragma unroll
        for (int tn = 0; tn < 8; tn++) {
            const int c0 = bn + wn * 64 + tn * 8 + 2 * qc;
            #pragma unroll
            for (int half = 0; half < 2; half++) {
                const int r = r0 + half * 8;
                float v0 = acc[tm][tn][half * 2 + 0];
                float v1 = acc[tm][tn][half * 2 + 1];
                if (bias) { v0 += bias[c0]; if (c0 + 1 < N) v1 += bias[c0 + 1]; }
                if (epi == 1) {
                    v0 = (v0 > 20.f) ? v0 : log1pf(expf(v0));
                    v1 = (v1 > 20.f) ? v1 : log1pf(expf(v1));
                }
                if (c0 + 1 < N) {
                    *(float2*)(C + (size_t)r * ldc + c0) = make_float2(v0, v1);
                } else if (c0 < N) {
                    C[(size_t)r * ldc + c0] = v0;
                }
            }
        }
    }
}

// ---------------- causal depthwise conv (K=4) + SiLU --------------------
__global__ __launch_bounds__(256)
void conv_silu_kernel(const float* __restrict__ conv_w, const float* __restrict__ conv_b)
{
    const size_t total = (size_t)BATCH * LSEQ * DINNER;
    size_t idx = (size_t)blockIdx.x * blockDim.x + threadIdx.x;
    if (idx >= total) return;
    const int d = (int)(idx % DINNER);
    const int l = (int)((idx / DINNER) % LSEQ);
    const int b = (int)(idx / ((size_t)DINNER * LSEQ));

    float acc = conv_b[d];
    #pragma unroll
    for (int k = 0; k < 4; k++) {
        const int ls = l - 3 + k;
        if (ls >= 0)
            acc = fmaf(conv_w[d * 4 + k],
                       g_xr[((size_t)b * LSEQ + ls) * (2 * DINNER) + d], acc);
    }
    g_xc[idx] = acc / (1.f + __expf(-acc));   // silu
}

// ---------------- selective scan over L (+x*D, fused gate) --------------
// one thread per (b, d); 64-thread blocks -> 128 blocks spread over SMs
__global__ __launch_bounds__(64)
void scan_kernel(const float* __restrict__ A_log, const float* __restrict__ D_par)
{
    const int d = blockIdx.x * 64 + threadIdx.x;   // 0..2047
    const int b = blockIdx.y;

    float A[NST];
    #pragma unroll
    for (int n = 0; n < NST; n++) A[n] = -expf(A_log[d * NST + n]);
    float h[NST];
    #pragma unroll
    for (int n = 0; n < NST; n++) h[n] = 0.f;
    const float Dp = D_par[d];

    const float* xdb = g_xdbl + (size_t)b * LSEQ * XDBLC;

    for (int l = 0; l < LSEQ; l++) {
        const size_t bl = (size_t)b * LSEQ + l;
        const size_t base = bl * DINNER + d;
        const float dt = g_dt[base];
        const float xt = g_xc[base];
        const float* BC = xdb + (size_t)l * XDBLC + DTR;
        const float dtx = dt * xt;
        float yt = 0.f;
        #pragma unroll
        for (int n = 0; n < NST; n++) {
            const float dA = __expf(dt * A[n]);
            h[n] = fmaf(h[n], dA, dtx * BC[n]);
            yt   = fmaf(h[n], BC[NST + n], yt);
        }
        const float r = g_xr[bl * (2 * DINNER) + DINNER + d];
        const float gate = r / (1.f + __expf(-r));
        g_xc[base] = fmaf(xt, Dp, yt) * gate;
    }
}

// ---------------- launch -------------------------------------------------
extern "C" void kernel_launch(void* const* d_in, const int* in_sizes, int n_in,
                              void* d_out, int out_size)
{
    const float* x      = (const float*)d_in[0];
    const float* W_in   = (const float*)d_in[1];
    const float* b_in   = (const float*)d_in[2];
    const float* conv_w = (const float*)d_in[3];
    const float* conv_b = (const float*)d_in[4];
    const float* W_x    = (const float*)d_in[5];
    const float* W_dt   = (const float*)d_in[6];
    const float* b_dt   = (const float*)d_in[7];
    const float* A_log  = (const float*)d_in[8];
    const float* D_par  = (const float*)d_in[9];
    const float* W_out  = (const float*)d_in[10];
    const float* b_out  = (const float*)d_in[11];
    float* out = (float*)d_out;

    float *xr, *xc, *xdbl, *dt;
    cudaGetSymbolAddress((void**)&xr,   g_xr);
    cudaGetSymbolAddress((void**)&xc,   g_xc);
    cudaGetSymbolAddress((void**)&xdbl, g_xdbl);
    cudaGetSymbolAddress((void**)&dt,   g_dt);

    const int M = BATCH * LSEQ;   // 16384

    // 1) in-projection: [M,1024] @ [1024,4096] -> g_xr
    mma_gemm<<<dim3((2 * DINNER) / BN, M / BM), 256>>>(
        x, W_in, b_in, xr, M, 2 * DINNER, DMODEL, DMODEL, 2 * DINNER, 2 * DINNER, 0);

    // 2) causal depthwise conv + silu -> g_xc
    {
        const size_t total = (size_t)M * DINNER;
        conv_silu_kernel<<<(unsigned)((total + 255) / 256), 256>>>(conv_w, conv_b);
    }

    // 3) x_dbl: [M,2048] @ [2048,96] -> g_xdbl
    mma_gemm<<<dim3(1, M / BM), 256>>>(
        xc, W_x, nullptr, xdbl, M, XDBLC, DINNER, DINNER, XDBLC, XDBLC, 0);

    // 4) delta: softplus([M,64] @ [64,2048] + b_dt) -> g_dt
    mma_gemm<<<dim3(DINNER / BN, M / BM), 256>>>(
        xdbl, W_dt, b_dt, dt, M, DINNER, DTR, XDBLC, DINNER, DINNER, 1);

    // 5) selective scan (y in place over g_xc, + x*D, * silu(res))
    scan_kernel<<<dim3(DINNER / 64, BATCH), 64>>>(A_log, D_par);

    // 6) out-projection: [M,2048] @ [2048,1024] + b_out -> d_out
    mma_gemm<<<dim3(DMODEL / BN, M / BM), 256>>>(
        xc, W_out, b_out, out, M, DMODEL, DINNER, DINNER, DMODEL, DMODEL, 0);
}

// round 3
// speedup vs baseline: 1.9789x; 1.6818x over previous
#include <cuda_runtime.h>
#include <math.h>
#include <stdint.h>

#define BATCH  4
#define LSEQ   4096
#define DMODEL 1024
#define DINNER 2048
#define DTR    64
#define NST    16
#define XDBLC  96   // dt_rank + 2*N

// ---------------- scratch (device globals) ----------------
__device__ float g_xr  [(size_t)BATCH * LSEQ * (2 * DINNER)];  // in-proj out (x | res)
__device__ float g_xc  [(size_t)BATCH * LSEQ * DINNER];        // conv+silu -> y(gated) in place
__device__ float g_xdbl[(size_t)BATCH * LSEQ * XDBLC];
__device__ float g_dt  [(size_t)BATCH * LSEQ * DINNER];

// ---------------- tf32 tensor-core GEMM (2xTF32, A pre-split in smem) ------
#define BM 128
#define BN 128
#define BKK 32
#define ALD 44    // (BKK + 12): 176B rows, 16B aligned, conflict-free frag loads
#define BLD 132   // (BN + 4): 528B rows, 16B aligned, conflict-free frag loads
#define SMEM_GEMM ((2 * BM * ALD + BKK * BLD) * 4)   // 61952 bytes

__device__ __forceinline__ uint32_t f2tf(float f) {
    uint32_t r; asm("cvt.rna.tf32.f32 %0, %1;" : "=r"(r) : "f"(f)); return r;
}

__device__ __forceinline__ void mma8(float* c,
    uint32_t a0, uint32_t a1, uint32_t a2, uint32_t a3, uint32_t b0, uint32_t b1)
{
    asm volatile(
        "mma.sync.aligned.m16n8k8.row.col.f32.tf32.tf32.f32 "
        "{%0,%1,%2,%3}, {%4,%5,%6,%7}, {%8,%9}, {%0,%1,%2,%3};"
        : "+f"(c[0]), "+f"(c[1]), "+f"(c[2]), "+f"(c[3])
        : "r"(a0), "r"(a1), "r"(a2), "r"(a3), "r"(b0), "r"(b1));
}

// C[M,N] = A[M,K] @ B[K,N] (+bias) (+softplus if epi==1)
// M % 128 == 0, K % 32 == 0; N arbitrary (guarded).
__global__ __launch_bounds__(256)
void mma_gemm(const float* __restrict__ A, const float* __restrict__ B,
              const float* __restrict__ bias, float* __restrict__ C,
              int M, int N, int K, int lda, int ldb, int ldc, int epi)
{
    extern __shared__ float smem[];
    float (*Ah)[ALD] = (float(*)[ALD])smem;                 // tf32 hi of A, [BM][ALD]
    float (*Al)[ALD] = (float(*)[ALD])(smem + BM * ALD);    // tf32 lo of A
    float (*Bs)[BLD] = (float(*)[BLD])(smem + 2 * BM * ALD);// tf32 B, [BKK][BLD]

    const int tid = threadIdx.x;
    const int bm = blockIdx.y * BM;
    const int bn = blockIdx.x * BN;

    const int wid = tid >> 5, lane = tid & 31;
    const int wm = wid >> 1, wn = wid & 1;         // 4 x 2 warps; warp tile 32x64
    const int qr = lane >> 2, qc = lane & 3;

    float acc[2][8][4];
    #pragma unroll
    for (int i = 0; i < 2; i++)
        #pragma unroll
        for (int j = 0; j < 8; j++)
            #pragma unroll
            for (int e = 0; e < 4; e++) acc[i][j][e] = 0.f;

    float4 ra[4], rb[4];

    auto loadA = [&](int kt) {
        #pragma unroll
        for (int t = 0; t < 4; t++) {
            const int f4 = tid + t * 256;
            const int r = f4 >> 3, c = (f4 & 7) * 4;
            ra[t] = *(const float4*)(A + (size_t)(bm + r) * lda + kt + c);
        }
    };
    auto loadB = [&](int kt) {
        #pragma unroll
        for (int t = 0; t < 4; t++) {
            const int f4 = tid + t * 256;
            const int k = f4 >> 5, c = (f4 & 31) * 4;
            const int n = bn + c;
            const float* p = B + (size_t)(kt + k) * ldb + n;
            if (n + 3 < N) {
                rb[t] = *(const float4*)p;
            } else {
                float4 v;
                v.x = (n + 0 < N) ? p[0] : 0.f;
                v.y = (n + 1 < N) ? p[1] : 0.f;
                v.z = (n + 2 < N) ? p[2] : 0.f;
                v.w = (n + 3 < N) ? p[3] : 0.f;
                rb[t] = v;
            }
        }
    };
    auto stS = [&]() {
        #pragma unroll
        for (int t = 0; t < 4; t++) {
            const int f4 = tid + t * 256;
            const int r = f4 >> 3, c = (f4 & 7) * 4;
            // split A into tf32 hi + lo once, at store time
            float4 hi, lo;
            hi.x = __uint_as_float(f2tf(ra[t].x)); lo.x = __uint_as_float(f2tf(ra[t].x - hi.x));
            hi.y = __uint_as_float(f2tf(ra[t].y)); lo.y = __uint_as_float(f2tf(ra[t].y - hi.y));
            hi.z = __uint_as_float(f2tf(ra[t].z)); lo.z = __uint_as_float(f2tf(ra[t].z - hi.z));
            hi.w = __uint_as_float(f2tf(ra[t].w)); lo.w = __uint_as_float(f2tf(ra[t].w - hi.w));
            *(float4*)&Ah[r][c] = hi;
            *(float4*)&Al[r][c] = lo;

            const int k = f4 >> 5, cb = (f4 & 31) * 4;
            float4 bv;
            bv.x = __uint_as_float(f2tf(rb[t].x));
            bv.y = __uint_as_float(f2tf(rb[t].y));
            bv.z = __uint_as_float(f2tf(rb[t].z));
            bv.w = __uint_as_float(f2tf(rb[t].w));
            *(float4*)&Bs[k][cb] = bv;
        }
    };

    loadA(0); loadB(0);

    for (int kt = 0; kt < K; kt += BKK) {
        stS();
        __syncthreads();
        if (kt + BKK < K) { loadA(kt + BKK); loadB(kt + BKK); }

        #pragma unroll
        for (int kk = 0; kk < BKK; kk += 8) {
            uint32_t ah[2][4], al[2][4];
            #pragma unroll
            for (int tm = 0; tm < 2; tm++) {
                const int r0 = wm * 32 + tm * 16 + qr;
                ah[tm][0] = __float_as_uint(Ah[r0    ][kk + qc]);
                ah[tm][1] = __float_as_uint(Ah[r0 + 8][kk + qc]);
                ah[tm][2] = __float_as_uint(Ah[r0    ][kk + qc + 4]);
                ah[tm][3] = __float_as_uint(Ah[r0 + 8][kk + qc + 4]);
                al[tm][0] = __float_as_uint(Al[r0    ][kk + qc]);
                al[tm][1] = __float_as_uint(Al[r0 + 8][kk + qc]);
                al[tm][2] = __float_as_uint(Al[r0    ][kk + qc + 4]);
                al[tm][3] = __float_as_uint(Al[r0 + 8][kk + qc + 4]);
            }
            #pragma unroll
            for (int tn = 0; tn < 8; tn++) {
                const int col = wn * 64 + tn * 8 + qr;
                const uint32_t b0 = __float_as_uint(Bs[kk + qc][col]);
                const uint32_t b1 = __float_as_uint(Bs[kk + qc + 4][col]);
                #pragma unroll
                for (int tm = 0; tm < 2; tm++) {
                    mma8(acc[tm][tn], al[tm][0], al[tm][1], al[tm][2], al[tm][3], b0, b1);
                    mma8(acc[tm][tn], ah[tm][0], ah[tm][1], ah[tm][2], ah[tm][3], b0, b1);
                }
            }
        }
        __syncthreads();
    }

    // ---- epilogue ----
    #pragma unroll
    for (int tm = 0; tm < 2; tm++) {
        const int r0 = bm + wm * 32 + tm * 16 + qr;
        #pragma unroll
        for (int tn = 0; tn < 8; tn++) {
            const int c0 = bn + wn * 64 + tn * 8 + 2 * qc;
            #pragma unroll
            for (int half = 0; half < 2; half++) {
                const int r = r0 + half * 8;
                float v0 = acc[tm][tn][half * 2 + 0];
                float v1 = acc[tm][tn][half * 2 + 1];
                if (bias && c0 < N) { v0 += bias[c0]; if (c0 + 1 < N) v1 += bias[c0 + 1]; }
                if (epi == 1) {
                    v0 = (v0 > 20.f) ? v0 : log1pf(expf(v0));
                    v1 = (v1 > 20.f) ? v1 : log1pf(expf(v1));
                }
                if (c0 + 1 < N) {
                    *(float2*)(C + (size_t)r * ldc + c0) = make_float2(v0, v1);
                } else if (c0 < N) {
                    C[(size_t)r * ldc + c0] = v0;
                }
            }
        }
    }
}

// ---------------- causal depthwise conv (K=4) + SiLU --------------------
__global__ __launch_bounds__(256)
void conv_silu_kernel(const float* __restrict__ conv_w, const float* __restrict__ conv_b)
{
    const size_t total = (size_t)BATCH * LSEQ * DINNER;
    size_t idx = (size_t)blockIdx.x * blockDim.x + threadIdx.x;
    if (idx >= total) return;
    const int d = (int)(idx % DINNER);
    const int l = (int)((idx / DINNER) % LSEQ);
    const int b = (int)(idx / ((size_t)DINNER * LSEQ));

    float acc = conv_b[d];
    #pragma unroll
    for (int k = 0; k < 4; k++) {
        const int ls = l - 3 + k;
        if (ls >= 0)
            acc = fmaf(conv_w[d * 4 + k],
                       g_xr[((size_t)b * LSEQ + ls) * (2 * DINNER) + d], acc);
    }
    g_xc[idx] = acc / (1.f + __expf(-acc));   // silu
}

// ---------------- selective scan over L (+x*D, fused gate) --------------
// one thread per (b,d). BC tile staged in smem; dt/xt/res prefetched one ahead.
#define SCAN_T 128
__global__ __launch_bounds__(64)
void scan_kernel(const float* __restrict__ A_log, const float* __restrict__ D_par)
{
    __shared__ float sBC[SCAN_T][32];

    const int tid = threadIdx.x;
    const int d = blockIdx.x * 64 + tid;   // 0..2047
    const int b = blockIdx.y;

    float A[NST];
    #pragma unroll
    for (int n = 0; n < NST; n++) A[n] = -expf(A_log[d * NST + n]);
    float h[NST];
    #pragma unroll
    for (int n = 0; n < NST; n++) h[n] = 0.f;
    const float Dp = D_par[d];

    // incremental pointers
    size_t pd = (size_t)b * LSEQ * DINNER + d;                       // g_dt / g_xc
    size_t pr = (size_t)b * LSEQ * (2 * DINNER) + DINNER + d;        // g_xr (res half)

    float dt_nx = g_dt[pd];
    float xt_nx = g_xc[pd];
    float rr_nx = g_xr[pr];

    const float* xdb = g_xdbl + (size_t)b * LSEQ * XDBLC + DTR;

    for (int c = 0; c < LSEQ / SCAN_T; c++) {
        __syncthreads();
        // cooperative load of BC tile: SCAN_T rows x 32 floats
        const float* src = xdb + (size_t)c * SCAN_T * XDBLC;
        #pragma unroll 4
        for (int i = tid; i < SCAN_T * 8; i += 64) {
            const int row = i >> 3, c4 = (i & 7) * 4;
            *(float4*)&sBC[row][c4] = *(const float4*)(src + (size_t)row * XDBLC + c4);
        }
        __syncthreads();

        for (int t = 0; t < SCAN_T; t++) {
            const float dt = dt_nx, xt = xt_nx, rr = rr_nx;
            const size_t pd_cur = pd;
            const int l = c * SCAN_T + t;
            pd += DINNER; pr += 2 * DINNER;
            if (l + 1 < LSEQ) {          // prefetch next timestep
                dt_nx = g_dt[pd];
                xt_nx = g_xc[pd];
                rr_nx = g_xr[pr];
            }

            const float dtx = dt * xt;
            float yt = 0.f;
            #pragma unroll
            for (int n = 0; n < NST; n++) {
                const float dA = __expf(dt * A[n]);
                h[n] = fmaf(h[n], dA, dtx * sBC[t][n]);
                yt   = fmaf(h[n], sBC[t][NST + n], yt);
            }
            const float gate = rr / (1.f + __expf(-rr));
            g_xc[pd_cur] = fmaf(xt, Dp, yt) * gate;
        }
    }
}

// ---------------- launch -------------------------------------------------
extern "C" void kernel_launch(void* const* d_in, const int* in_sizes, int n_in,
                              void* d_out, int out_size)
{
    const float* x      = (const float*)d_in[0];
    const float* W_in   = (const float*)d_in[1];
    const float* b_in   = (const float*)d_in[2];
    const float* conv_w = (const float*)d_in[3];
    const float* conv_b = (const float*)d_in[4];
    const float* W_x    = (const float*)d_in[5];
    const float* W_dt   = (const float*)d_in[6];
    const float* b_dt   = (const float*)d_in[7];
    const float* A_log  = (const float*)d_in[8];
    const float* D_par  = (const float*)d_in[9];
    const float* W_out  = (const float*)d_in[10];
    const float* b_out  = (const float*)d_in[11];
    float* out = (float*)d_out;

    float *xr, *xc, *xdbl, *dt;
    cudaGetSymbolAddress((void**)&xr,   g_xr);
    cudaGetSymbolAddress((void**)&xc,   g_xc);
    cudaGetSymbolAddress((void**)&xdbl, g_xdbl);
    cudaGetSymbolAddress((void**)&dt,   g_dt);

    cudaFuncSetAttribute(mma_gemm, cudaFuncAttributeMaxDynamicSharedMemorySize, SMEM_GEMM);

    const int M = BATCH * LSEQ;   // 16384

    // 1) in-projection: [M,1024] @ [1024,4096] -> g_xr
    mma_gemm<<<dim3((2 * DINNER) / BN, M / BM), 256, SMEM_GEMM>>>(
        x, W_in, b_in, xr, M, 2 * DINNER, DMODEL, DMODEL, 2 * DINNER, 2 * DINNER, 0);

    // 2) causal depthwise conv + silu -> g_xc
    {
        const size_t total = (size_t)M * DINNER;
        conv_silu_kernel<<<(unsigned)((total + 255) / 256), 256>>>(conv_w, conv_b);
    }

    // 3) x_dbl: [M,2048] @ [2048,96] -> g_xdbl
    mma_gemm<<<dim3(1, M / BM), 256, SMEM_GEMM>>>(
        xc, W_x, nullptr, xdbl, M, XDBLC, DINNER, DINNER, XDBLC, XDBLC, 0);

    // 4) delta: softplus([M,64] @ [64,2048] + b_dt) -> g_dt
    mma_gemm<<<dim3(DINNER / BN, M / BM), 256, SMEM_GEMM>>>(
        xdbl, W_dt, b_dt, dt, M, DINNER, DTR, XDBLC, DINNER, DINNER, 1);

    // 5) selective scan (y in place over g_xc, + x*D, * silu(res))
    scan_kernel<<<dim3(DINNER / 64, BATCH), 64>>>(A_log, D_par);

    // 6) out-projection: [M,2048] @ [2048,1024] + b_out -> d_out
    mma_gemm<<<dim3(DMODEL / BN, M / BM), 256, SMEM_GEMM>>>(
        xc, W_out, b_out, out, M, DMODEL, DINNER, DINNER, DMODEL, DMODEL, 0);
}